// round 2
// baseline (speedup 1.0000x reference)
#include <cuda_runtime.h>

#define B_ 32
#define Q_ 16
#define K_ 4096
#define D_ 128
#define V_ 128
#define KC 64
#define THREADS 256
#define SCALE 0.08838834764831845f  /* 1/sqrt(128) */

// scratch for attn if harness only validates `output`
__device__ float g_attn_scratch[(size_t)B_ * Q_ * K_];

__global__ __launch_bounds__(THREADS, 4)
void inv_attn_kernel(const float4* __restrict__ query4,
                     const float4* __restrict__ key4,
                     const float4* __restrict__ value4,
                     float* __restrict__ out,       // [B,Q,V] (REDG-accumulated, pre-zeroed)
                     float* __restrict__ attn_out)  // [B,Q,K]
{
    __shared__ float  qs[Q_ * D_];        // 8 KB  scaled query
    __shared__ float  att[Q_ * KC];       // 4 KB  logits -> attention tile
    __shared__ float4 vt[KC * (V_ / 4)];  // 32 KB value tile

    const int b    = blockIdx.y;
    const int k0   = blockIdx.x * KC;
    const int tid  = threadIdx.x;
    const int warp = tid >> 5;
    const int lane = tid & 31;

    // ---- stage query (scaled) and value tile ----
    for (int i = tid; i < Q_ * D_ / 4; i += THREADS) {
        float4 v = query4[b * (Q_ * D_ / 4) + i];
        v.x *= SCALE; v.y *= SCALE; v.z *= SCALE; v.w *= SCALE;
        reinterpret_cast<float4*>(qs)[i] = v;
    }
    for (int i = tid; i < KC * V_ / 4; i += THREADS)
        vt[i] = value4[((size_t)b * K_ + k0) * (V_ / 4) + i];
    __syncthreads();

    // ---- phase 1: logits. Each warp owns 8 keys per q.
    // Half-warp per key row: lanes 0-15 -> row pair*2, lanes 16-31 -> row pair*2+1.
    {
        const int half = lane >> 4;          // 0/1 : which row of the pair
        const int d4   = lane & 15;          // float4 index within half-row
        const int kw   = k0 + warp * 8;      // this warp's first key

        for (int q = 0; q < Q_; q++) {
            // q fragments this lane needs: float4 d4 and d4+16
            float4 qa = reinterpret_cast<const float4*>(qs)[q * 32 + d4];
            float4 qb = reinterpret_cast<const float4*>(qs)[q * 32 + d4 + 16];
            const float4* kbase =
                key4 + ((size_t)(b * Q_ + q) * K_ + kw) * (D_ / 4);

            #pragma unroll
            for (int pr = 0; pr < 4; pr++) {          // 4 pairs = 8 keys
                const float4* kp = kbase + (size_t)(pr * 2 + half) * 32;
                float4 ka = kp[d4];                    // front half of row
                float4 kb = kp[d4 + 16];               // back half of row
                float p = qa.x * ka.x + qa.y * ka.y + qa.z * ka.z + qa.w * ka.w
                        + qb.x * kb.x + qb.y * kb.y + qb.z * kb.z + qb.w * kb.w;
                p += __shfl_xor_sync(0xffffffffu, p, 1);
                p += __shfl_xor_sync(0xffffffffu, p, 2);
                p += __shfl_xor_sync(0xffffffffu, p, 4);
                p += __shfl_xor_sync(0xffffffffu, p, 8);
                if (d4 == 0)                           // lanes 0 and 16 write
                    att[q * KC + warp * 8 + pr * 2 + half] = p;
            }
        }
    }
    __syncthreads();

    // ---- phase 2: softmax over q (axis=-2); thread t < KC owns key t ----
    if (tid < KC) {
        float l[Q_];
        float mx = -1e30f;
        #pragma unroll
        for (int q = 0; q < Q_; q++) {
            l[q] = att[q * KC + tid];
            mx = fmaxf(mx, l[q]);
        }
        float s = 0.0f;
        #pragma unroll
        for (int q = 0; q < Q_; q++) {
            l[q] = __expf(l[q] - mx);
            s += l[q];
        }
        float inv = 1.0f / s;
        #pragma unroll
        for (int q = 0; q < Q_; q++) {
            float a = l[q] * inv;
            att[q * KC + tid] = a;
            attn_out[(size_t)(b * Q_ + q) * K_ + k0 + tid] = a;
        }
    }
    __syncthreads();

    // ---- phase 3: out[b,q,vc*8..+8] += sum_k attn[q,k] * value[k, vc*8..+8] ----
    {
        const int q  = tid >> 4;   // 0..15
        const int vc = tid & 15;   // 0..15, owns 8 consecutive v floats
        float4 a0 = make_float4(0.f, 0.f, 0.f, 0.f);
        float4 a1 = make_float4(0.f, 0.f, 0.f, 0.f);

        #pragma unroll 8
        for (int kk = 0; kk < KC; kk++) {
            float  a  = att[q * KC + kk];       // broadcast within 16-lane group
            float4 v0 = vt[kk * 32 + vc * 2];
            float4 v1 = vt[kk * 32 + vc * 2 + 1];
            a0.x += a * v0.x; a0.y += a * v0.y; a0.z += a * v0.z; a0.w += a * v0.w;
            a1.x += a * v1.x; a1.y += a * v1.y; a1.z += a * v1.z; a1.w += a * v1.w;
        }
        float* o = out + (size_t)(b * Q_ + q) * V_ + vc * 8;
        atomicAdd(o + 0, a0.x); atomicAdd(o + 1, a0.y);
        atomicAdd(o + 2, a0.z); atomicAdd(o + 3, a0.w);
        atomicAdd(o + 4, a1.x); atomicAdd(o + 5, a1.y);
        atomicAdd(o + 6, a1.z); atomicAdd(o + 7, a1.w);
    }
}

extern "C" void kernel_launch(void* const* d_in, const int* in_sizes, int n_in,
                              void* d_out, int out_size)
{
    const float4* query = (const float4*)d_in[0];
    const float4* key   = (const float4*)d_in[1];
    const float4* value = (const float4*)d_in[2];

    float* out = (float*)d_out;
    float* attn;
    const int out_elems  = B_ * Q_ * V_;        // 65536
    const int attn_elems = B_ * Q_ * K_;        // 2097152

    if (out_size >= out_elems + attn_elems) {
        attn = out + out_elems;                 // (output, attn) concatenated
    } else {
        cudaGetSymbolAddress((void**)&attn, g_attn_scratch);
    }

    // zero the accumulated output region (graph-capturable)
    cudaMemsetAsync(d_out, 0, (size_t)out_elems * sizeof(float));

    dim3 grid(K_ / KC, B_);
    inv_attn_kernel<<<grid, THREADS>>>(query, key, value, out, attn);
}

// round 3
// speedup vs baseline: 1.2795x; 1.2795x over previous
#include <cuda_runtime.h>

#define B_ 32
#define Q_ 16
#define K_ 4096
#define D_ 128
#define V_ 128
#define KC 128
#define KCP 129          /* padded row to kill bank conflicts */
#define THREADS 256
#define GRID 512
#define TILES 1024       /* (K_/KC) * B_ */
#define REPS (TILES / GRID)
#define SCALE 0.08838834764831845f  /* 1/sqrt(128) */

// scratch for attn if harness only validates `output`
__device__ float g_attn_scratch[(size_t)B_ * Q_ * K_];

__device__ __forceinline__ void red_add_v4(float* p, float4 v) {
    asm volatile("red.global.add.v4.f32 [%0], {%1,%2,%3,%4};"
                 :: "l"(p), "f"(v.x), "f"(v.y), "f"(v.z), "f"(v.w) : "memory");
}

__global__ __launch_bounds__(THREADS, 4)
void inv_attn_kernel(const float4* __restrict__ query4,
                     const float4* __restrict__ key4,
                     const float4* __restrict__ value4,
                     float* __restrict__ out,       // [B,Q,V] pre-zeroed, RED-accumulated
                     float* __restrict__ attn_out)  // [B,Q,K]
{
    __shared__ float qs[Q_ * D_];    // 8 KB scaled query
    __shared__ float att[Q_][KCP];   // 8.25 KB logits -> attention

    const int tid  = threadIdx.x;
    const int warp = tid >> 5;
    const int lane = tid & 31;

    #pragma unroll 1
    for (int rep = 0; rep < REPS; rep++) {
        const int t  = blockIdx.x + rep * GRID;   // flat tile id
        const int b  = t >> 5;                    // 32 tiles per batch
        const int k0 = (t & 31) * KC;

        // ---- stage scaled query for this batch ----
        for (int i = tid; i < Q_ * D_ / 4; i += THREADS) {
            float4 v = query4[b * (Q_ * D_ / 4) + i];
            v.x *= SCALE; v.y *= SCALE; v.z *= SCALE; v.w *= SCALE;
            reinterpret_cast<float4*>(qs)[i] = v;
        }
        __syncthreads();

        // ---- phase 1: logits[q][k]; warp owns 16 contiguous keys ----
        {
            const int kw = k0 + warp * 16;
            for (int q = 0; q < Q_; q++) {
                float4 qv = reinterpret_cast<const float4*>(qs)[q * 32 + lane];
                const float4* kp =
                    key4 + ((size_t)(b * Q_ + q) * K_ + kw) * (D_ / 4);
                #pragma unroll 4
                for (int kk = 0; kk < 16; kk++) {
                    float4 kv = kp[kk * 32 + lane];   // 512B coalesced row
                    float p = qv.x * kv.x + qv.y * kv.y
                            + qv.z * kv.z + qv.w * kv.w;
                    p += __shfl_xor_sync(0xffffffffu, p, 16);
                    p += __shfl_xor_sync(0xffffffffu, p, 8);
                    p += __shfl_xor_sync(0xffffffffu, p, 4);
                    p += __shfl_xor_sync(0xffffffffu, p, 2);
                    p += __shfl_xor_sync(0xffffffffu, p, 1);
                    if (lane == 0) att[q][warp * 16 + kk] = p;
                }
            }
        }
        __syncthreads();

        // ---- phase 2: softmax over q (axis=-2); thread t < KC owns key t ----
        if (tid < KC) {
            float l[Q_];
            float mx = -1e30f;
            #pragma unroll
            for (int q = 0; q < Q_; q++) {
                l[q] = att[q][tid];
                mx = fmaxf(mx, l[q]);
            }
            float s = 0.0f;
            #pragma unroll
            for (int q = 0; q < Q_; q++) {
                l[q] = __expf(l[q] - mx);
                s += l[q];
            }
            float inv = 1.0f / s;
            #pragma unroll
            for (int q = 0; q < Q_; q++) {
                float a = l[q] * inv;
                att[q][tid] = a;
                attn_out[(size_t)(b * Q_ + q) * K_ + k0 + tid] = a;
            }
        }
        __syncthreads();

        // ---- phase 3: out[b,q,vc*8..+8] += sum_k att[q][k] * value[k][...] ----
        // q = tid&15 -> att reads stride-KCP = conflict-free;
        // vc = tid>>4 -> value loads are 16-lane broadcasts (streamed once).
        {
            const int q  = tid & 15;
            const int vc = tid >> 4;
            float4 a0 = make_float4(0.f, 0.f, 0.f, 0.f);
            float4 a1 = make_float4(0.f, 0.f, 0.f, 0.f);

            const float4* vp =
                value4 + ((size_t)b * K_ + k0) * (V_ / 4) + vc * 2;
            #pragma unroll 4
            for (int kk = 0; kk < KC; kk++) {
                float  a  = att[q][kk];
                float4 v0 = vp[kk * 32];
                float4 v1 = vp[kk * 32 + 1];
                a0.x += a * v0.x; a0.y += a * v0.y;
                a0.z += a * v0.z; a0.w += a * v0.w;
                a1.x += a * v1.x; a1.y += a * v1.y;
                a1.z += a * v1.z; a1.w += a * v1.w;
            }
            float* o = out + (size_t)(b * Q_ + q) * V_ + vc * 8;
            red_add_v4(o,     a0);
            red_add_v4(o + 4, a1);
        }
        __syncthreads();   // protect qs/att before next tile
    }
}

extern "C" void kernel_launch(void* const* d_in, const int* in_sizes, int n_in,
                              void* d_out, int out_size)
{
    const float4* query = (const float4*)d_in[0];
    const float4* key   = (const float4*)d_in[1];
    const float4* value = (const float4*)d_in[2];

    float* out = (float*)d_out;
    float* attn;
    const int out_elems  = B_ * Q_ * V_;        // 65536
    const int attn_elems = B_ * Q_ * K_;        // 2097152

    if (out_size >= out_elems + attn_elems) {
        attn = out + out_elems;                 // (output, attn) concatenated
    } else {
        cudaGetSymbolAddress((void**)&attn, g_attn_scratch);
    }

    cudaMemsetAsync(d_out, 0, (size_t)out_elems * sizeof(float));

    inv_attn_kernel<<<GRID, THREADS>>>(query, key, value, out, attn);
}

// round 4
// speedup vs baseline: 1.4950x; 1.1684x over previous
#include <cuda_runtime.h>

#define B_ 32
#define Q_ 16
#define K_ 4096
#define D_ 128
#define V_ 128
#define THREADS 128        /* 4 warps per block */
#define NWARP 4
#define GRID 512           /* 2048 warps x 64 keys = 32*4096 */
#define KW 64              /* keys per warp */
#define CHUNK 32           /* keys per smem chunk */
#define SCALE 0.08838834764831845f  /* 1/sqrt(128) */

// scratch for attn if harness only validates `output`
__device__ float g_attn_scratch[(size_t)B_ * Q_ * K_];

__device__ __forceinline__ void red_add_v4(float* p, float4 v) {
    asm volatile("red.global.add.v4.f32 [%0], {%1,%2,%3,%4};"
                 :: "l"(p), "f"(v.x), "f"(v.y), "f"(v.z), "f"(v.w) : "memory");
}

__global__ __launch_bounds__(THREADS, 4)
void inv_attn_kernel(const float4* __restrict__ query4,
                     const float4* __restrict__ key4,
                     const float4* __restrict__ value4,
                     float* __restrict__ out,       // [B,Q,V] pre-zeroed, RED-accumulated
                     float* __restrict__ attn_out)  // [B,Q,K]
{
    __shared__ float att[NWARP][Q_][CHUNK];   // 8 KB, warp-private slabs

    const int warp = threadIdx.x >> 5;
    const int lane = threadIdx.x & 31;
    const int gw   = blockIdx.x * NWARP + warp;   // 0..2047
    const int b    = gw >> 6;                     // 64 warps per batch
    const int kbase = (gw & 63) * KW;             // this warp's first key

    float4 acc[Q_];
    #pragma unroll
    for (int q = 0; q < Q_; q++) acc[q] = make_float4(0.f, 0.f, 0.f, 0.f);

    #pragma unroll 1
    for (int c = 0; c < KW / CHUNK; c++) {
        const int k0 = kbase + c * CHUNK;

        // ---- phase 1: logits[q][kk] for this warp's 32 keys ----
        for (int q = 0; q < Q_; q++) {
            float4 qv = query4[(b * Q_ + q) * (D_ / 4) + lane];
            qv.x *= SCALE; qv.y *= SCALE; qv.z *= SCALE; qv.w *= SCALE;
            const float4* kp =
                key4 + ((size_t)(b * Q_ + q) * K_ + k0) * (D_ / 4);
            #pragma unroll 8
            for (int kk = 0; kk < CHUNK; kk++) {
                float4 kv = kp[kk * 32 + lane];     // 512B coalesced row
                float p = qv.x * kv.x + qv.y * kv.y
                        + qv.z * kv.z + qv.w * kv.w;
                p += __shfl_xor_sync(0xffffffffu, p, 16);
                p += __shfl_xor_sync(0xffffffffu, p, 8);
                p += __shfl_xor_sync(0xffffffffu, p, 4);
                p += __shfl_xor_sync(0xffffffffu, p, 2);
                p += __shfl_xor_sync(0xffffffffu, p, 1);
                if (lane == 0) att[warp][q][kk] = p;
            }
        }
        __syncwarp();

        // ---- phase 2: softmax over q (axis=-2); lane owns key k0+lane ----
        {
            float l[Q_];
            float mx = -1e30f;
            #pragma unroll
            for (int q = 0; q < Q_; q++) {
                l[q] = att[warp][q][lane];          // conflict-free row read
                mx = fmaxf(mx, l[q]);
            }
            float s = 0.0f;
            #pragma unroll
            for (int q = 0; q < Q_; q++) {
                l[q] = __expf(l[q] - mx);
                s += l[q];
            }
            float inv = 1.0f / s;
            #pragma unroll
            for (int q = 0; q < Q_; q++) {
                float a = l[q] * inv;
                att[warp][q][lane] = a;
                attn_out[(size_t)(b * Q_ + q) * K_ + k0 + lane] = a;  // 128B coalesced
            }
        }
        __syncwarp();

        // ---- phase 3: acc[q] += att[q][kk] * value[k0+kk][lane*4..+4] ----
        {
            const float4* vp =
                value4 + ((size_t)b * K_ + k0) * (V_ / 4) + lane;
            #pragma unroll 4
            for (int kk = 0; kk < CHUNK; kk++) {
                float4 vv = vp[kk * 32];            // 512B coalesced row
                #pragma unroll
                for (int q = 0; q < Q_; q++) {
                    float a = att[warp][q][kk];     // LDS broadcast
                    acc[q].x += a * vv.x;
                    acc[q].y += a * vv.y;
                    acc[q].z += a * vv.z;
                    acc[q].w += a * vv.w;
                }
            }
        }
        __syncwarp();   // att reused next chunk
    }

    // ---- flush: one RED.v4 per (q) per lane ----
    float* o = out + (size_t)b * Q_ * V_ + lane * 4;
    #pragma unroll
    for (int q = 0; q < Q_; q++)
        red_add_v4(o + q * V_, acc[q]);
}

extern "C" void kernel_launch(void* const* d_in, const int* in_sizes, int n_in,
                              void* d_out, int out_size)
{
    const float4* query = (const float4*)d_in[0];
    const float4* key   = (const float4*)d_in[1];
    const float4* value = (const float4*)d_in[2];

    float* out = (float*)d_out;
    float* attn;
    const int out_elems  = B_ * Q_ * V_;        // 65536
    const int attn_elems = B_ * Q_ * K_;        // 2097152

    if (out_size >= out_elems + attn_elems) {
        attn = out + out_elems;                 // (output, attn) concatenated
    } else {
        cudaGetSymbolAddress((void**)&attn, g_attn_scratch);
    }

    cudaMemsetAsync(d_out, 0, (size_t)out_elems * sizeof(float));

    inv_attn_kernel<<<GRID, THREADS>>>(query, key, value, out, attn);
}

// round 5
// speedup vs baseline: 1.5596x; 1.0432x over previous
#include <cuda_runtime.h>

#define B_ 32
#define Q_ 16
#define K_ 4096
#define D_ 128
#define V_ 128
#define THREADS 128        /* 4 warps per block */
#define NWARP 4
#define GRID 512           /* 2048 warps x 64 keys = 32*4096 */
#define KW 64              /* keys per warp */
#define CHUNK 32           /* keys per smem chunk */
#define SCALE 0.08838834764831845f  /* 1/sqrt(128) */

// scratch for attn if harness only validates `output`
__device__ float g_attn_scratch[(size_t)B_ * Q_ * K_];

__device__ __forceinline__ void red_add_v4(float* p, float4 v) {
    asm volatile("red.global.add.v4.f32 [%0], {%1,%2,%3,%4};"
                 :: "l"(p), "f"(v.x), "f"(v.y), "f"(v.z), "f"(v.w) : "memory");
}

__device__ __forceinline__ void cp_async16(void* smem_dst, const void* gsrc) {
    unsigned s = (unsigned)__cvta_generic_to_shared(smem_dst);
    asm volatile("cp.async.cg.shared.global [%0], [%1], 16;"
                 :: "r"(s), "l"(gsrc));
}
__device__ __forceinline__ void cp_async_commit() {
    asm volatile("cp.async.commit_group;");
}
__device__ __forceinline__ void cp_async_wait_all() {
    asm volatile("cp.async.wait_group 0;");
}

__global__ __launch_bounds__(THREADS, 4)
void inv_attn_kernel(const float4* __restrict__ query4,
                     const float4* __restrict__ key4,
                     const float4* __restrict__ value4,
                     float* __restrict__ out,       // [B,Q,V] pre-zeroed, RED-accumulated
                     float* __restrict__ attn_out)  // [B,Q,K]
{
    __shared__ float  att[NWARP][Q_][CHUNK];   // 8 KB
    __shared__ float4 vt[NWARP][16][V_ / 4];   // 32 KB, 16 value rows per warp

    const int warp = threadIdx.x >> 5;
    const int lane = threadIdx.x & 31;
    const int gw   = blockIdx.x * NWARP + warp;   // 0..2047
    const int b    = gw >> 6;                     // 64 warps per batch
    const int kbase = (gw & 63) * KW;             // this warp's first key

    float4 acc[Q_];
    #pragma unroll
    for (int q = 0; q < Q_; q++) acc[q] = make_float4(0.f, 0.f, 0.f, 0.f);

    #pragma unroll 1
    for (int c = 0; c < KW / CHUNK; c++) {
        const int k0 = kbase + c * CHUNK;
        const float4* vp = value4 + ((size_t)b * K_ + k0) * (V_ / 4) + lane;

        // ---- prefetch value rows 0-15 of this chunk (lands under ph1) ----
        #pragma unroll
        for (int r = 0; r < 16; r++)
            cp_async16(&vt[warp][r][lane], vp + r * 32);
        cp_async_commit();

        // ---- phase 1: logits[q][kk] for this warp's 32 keys ----
        for (int q = 0; q < Q_; q++) {
            float4 qv = query4[(b * Q_ + q) * (D_ / 4) + lane];
            qv.x *= SCALE; qv.y *= SCALE; qv.z *= SCALE; qv.w *= SCALE;
            const float4* kp =
                key4 + ((size_t)(b * Q_ + q) * K_ + k0) * (D_ / 4);
            #pragma unroll 8
            for (int kk = 0; kk < CHUNK; kk++) {
                float4 kv = __ldcs(kp + kk * 32 + lane);   // streaming 512B row
                float p = qv.x * kv.x + qv.y * kv.y
                        + qv.z * kv.z + qv.w * kv.w;
                p += __shfl_xor_sync(0xffffffffu, p, 16);
                p += __shfl_xor_sync(0xffffffffu, p, 8);
                p += __shfl_xor_sync(0xffffffffu, p, 4);
                p += __shfl_xor_sync(0xffffffffu, p, 2);
                p += __shfl_xor_sync(0xffffffffu, p, 1);
                if (lane == 0) att[warp][q][kk] = p;
            }
        }
        __syncwarp();

        // ---- phase 2: softmax over q (axis=-2); lane owns key k0+lane ----
        {
            float l[Q_];
            float mx = -1e30f;
            #pragma unroll
            for (int q = 0; q < Q_; q++) {
                l[q] = att[warp][q][lane];
                mx = fmaxf(mx, l[q]);
            }
            float s = 0.0f;
            #pragma unroll
            for (int q = 0; q < Q_; q++) {
                l[q] = __expf(l[q] - mx);
                s += l[q];
            }
            float inv = 1.0f / s;
            #pragma unroll
            for (int q = 0; q < Q_; q++) {
                float a = l[q] * inv;
                att[warp][q][lane] = a;
                __stcs(&attn_out[(size_t)(b * Q_ + q) * K_ + k0 + lane], a);
            }
        }
        __syncwarp();

        // ---- phase 3a: rows 0-15 from smem ----
        cp_async_wait_all();
        __syncwarp();
        #pragma unroll 4
        for (int kk = 0; kk < 16; kk++) {
            float4 vv = vt[warp][kk][lane];          // conflict-free LDS.128
            #pragma unroll
            for (int q = 0; q < Q_; q++) {
                float a = att[warp][q][kk];          // LDS broadcast
                acc[q].x += a * vv.x;
                acc[q].y += a * vv.y;
                acc[q].z += a * vv.z;
                acc[q].w += a * vv.w;
            }
        }
        __syncwarp();

        // ---- prefetch + phase 3b: rows 16-31 ----
        #pragma unroll
        for (int r = 0; r < 16; r++)
            cp_async16(&vt[warp][r][lane], vp + (16 + r) * 32);
        cp_async_commit();
        cp_async_wait_all();
        __syncwarp();
        #pragma unroll 4
        for (int kk = 0; kk < 16; kk++) {
            float4 vv = vt[warp][kk][lane];
            #pragma unroll
            for (int q = 0; q < Q_; q++) {
                float a = att[warp][q][kk + 16];
                acc[q].x += a * vv.x;
                acc[q].y += a * vv.y;
                acc[q].z += a * vv.z;
                acc[q].w += a * vv.w;
            }
        }
        __syncwarp();   // att + vt reused next chunk
    }

    // ---- flush: one RED.v4 per q per lane ----
    float* o = out + (size_t)b * Q_ * V_ + lane * 4;
    #pragma unroll
    for (int q = 0; q < Q_; q++)
        red_add_v4(o + q * V_, acc[q]);
}

extern "C" void kernel_launch(void* const* d_in, const int* in_sizes, int n_in,
                              void* d_out, int out_size)
{
    const float4* query = (const float4*)d_in[0];
    const float4* key   = (const float4*)d_in[1];
    const float4* value = (const float4*)d_in[2];

    float* out = (float*)d_out;
    float* attn;
    const int out_elems  = B_ * Q_ * V_;        // 65536
    const int attn_elems = B_ * Q_ * K_;        // 2097152

    if (out_size >= out_elems + attn_elems) {
        attn = out + out_elems;                 // (output, attn) concatenated
    } else {
        cudaGetSymbolAddress((void**)&attn, g_attn_scratch);
    }

    cudaMemsetAsync(d_out, 0, (size_t)out_elems * sizeof(float));

    inv_attn_kernel<<<GRID, THREADS>>>(query, key, value, out, attn);
}